// round 16
// baseline (speedup 1.0000x reference)
#include <cuda_runtime.h>
#include <cuda_bf16.h>
#include <cstdint>

// ---------------------------------------------------------------------------
// ESABotRGCN 4-layer pipeline.
//  - Activations stored as TWO bf16 planes (hi, lo): producers split once,
//    GEMMs cp.async the planes and ldmatrix directly (no in-loop convert).
//  - emb_pipe: K=1536 fused embeddings, 128-row tiles, 2-deep cp.async.
//  - sq_pipe:  K=128 / K=384 GEMMs, 64-row tiles, 3 blocks/SM.
//  - RGCN layer: aggregate-first (mean commutes with linear map).
// ---------------------------------------------------------------------------
#define NMAX 100000
#define EMAX 600000

typedef __nv_bfloat16 bf16;

// ------------------------- scratch (device globals) ------------------------
__device__ bf16 g_xhA[(size_t)NMAX * 128];
__device__ bf16 g_xlA[(size_t)NMAX * 128];
__device__ bf16 g_xhB[(size_t)NMAX * 128];
__device__ bf16 g_xlB[(size_t)NMAX * 128];
__device__ bf16 g_zh [(size_t)NMAX * 256];
__device__ bf16 g_zl [(size_t)NMAX * 256];

__device__ bf16 g_Whi[14 * 128 * 128]; // [mat][n][k]  (W^T, split hi)
__device__ bf16 g_Wlo[14 * 128 * 128];
__device__ bf16 g_Ehi[64 * 1536];      // embedding W, block-diag
__device__ bf16 g_Elo[64 * 1536];

__device__ int g_c0[NMAX];
__device__ int g_c1[NMAX];
__device__ int g_rp[NMAX + 1];
__device__ int g_cur[NMAX];
__device__ int g_ep[EMAX];             // (src<<1)|rel
__device__ int g_bsum[128];
__device__ int g_boff[128];

// ------------------------------ small helpers ------------------------------
__device__ __forceinline__ float lrelu(float v) { return fmaxf(v, 0.01f * v); }

__device__ __forceinline__ void mma16816(float* c, const uint32_t* a,
                                         uint32_t b0, uint32_t b1) {
    asm volatile(
        "mma.sync.aligned.m16n8k16.row.col.f32.bf16.bf16.f32 "
        "{%0,%1,%2,%3}, {%4,%5,%6,%7}, {%8,%9}, {%0,%1,%2,%3};"
        : "+f"(c[0]), "+f"(c[1]), "+f"(c[2]), "+f"(c[3])
        : "r"(a[0]), "r"(a[1]), "r"(a[2]), "r"(a[3]), "r"(b0), "r"(b1));
}

__device__ __forceinline__ void ldsm4(uint32_t* r, uint32_t a) {
    asm volatile("ldmatrix.sync.aligned.m8n8.x4.shared.b16 {%0,%1,%2,%3}, [%4];"
                 : "=r"(r[0]), "=r"(r[1]), "=r"(r[2]), "=r"(r[3]) : "r"(a));
}
__device__ __forceinline__ void ldsm2(uint32_t& r0, uint32_t& r1, uint32_t a) {
    asm volatile("ldmatrix.sync.aligned.m8n8.x2.shared.b16 {%0,%1}, [%2];"
                 : "=r"(r0), "=r"(r1) : "r"(a));
}

// pack two fp32 -> bf16x2 {lo-addr=first, hi-addr=second}, rn
__device__ __forceinline__ uint32_t bfpack(float lo, float hi) {
    uint32_t r;
    asm("cvt.rn.bf16x2.f32 %0, %1, %2;" : "=r"(r) : "f"(hi), "f"(lo));
    return r;
}

// split two fp32 into hi/lo bf16 planes at element index idx (pair store)
__device__ __forceinline__ void store_split(bf16* ph, bf16* pl, size_t idx,
                                            float a, float b) {
    uint32_t hp = bfpack(a, b);
    float h0 = __uint_as_float(hp << 16);
    float h1 = __uint_as_float(hp & 0xffff0000u);
    *(uint32_t*)(ph + idx) = hp;
    *(uint32_t*)(pl + idx) = bfpack(a - h0, b - h1);
}

// Build hi/lo bf16 A fragments (m16k16) from fp32 stage (272B rows) — emb only
__device__ __forceinline__ void frag_cvt(uint32_t* ah, uint32_t* al,
                                         const char* stg, int row0, int ks,
                                         int lane) {
    const char* base = stg + (row0 + (lane >> 2)) * 272 +
                       (ks * 16 + 2 * (lane & 3)) * 4;
    float2 f[4];
    f[0] = *(const float2*)base;
    f[1] = *(const float2*)(base + 8 * 272);
    f[2] = *(const float2*)(base + 32);
    f[3] = *(const float2*)(base + 8 * 272 + 32);
#pragma unroll
    for (int i = 0; i < 4; i++) {
        uint32_t hp = bfpack(f[i].x, f[i].y);
        float h0 = __uint_as_float(hp << 16);
        float h1 = __uint_as_float(hp & 0xffff0000u);
        ah[i] = hp;
        al[i] = bfpack(f[i].x - h0, f[i].y - h1);
    }
}

// ------------------------------- weight prep -------------------------------
__global__ void k_wprep(const float* __restrict__ Win,
                        const float* __restrict__ Wroot,
                        const float* __restrict__ Wrel,
                        const float* __restrict__ Wo1) {
    int idx = blockIdx.x * blockDim.x + threadIdx.x;
    if (idx >= 14 * 16384) return;
    int m = idx >> 14;
    int r = idx & 16383;
    int n = r >> 7, k = r & 127;
    const float* src;
    if (m == 0) src = Win;
    else if (m == 13) src = Wo1;
    else {
        int l = (m - 1) / 3, j = (m - 1) % 3;
        src = (j == 0) ? (Wroot + (size_t)l * 16384)
                       : (Wrel + (size_t)(l * 2 + (j - 1)) * 16384);
    }
    float v = src[k * 128 + n];
    bf16 h = __float2bfloat16(v);
    g_Whi[idx] = h;
    g_Wlo[idx] = __float2bfloat16(v - __bfloat162float(h));
}

__global__ void k_eprep(const float* __restrict__ Wd,
                        const float* __restrict__ Wt) {
    int idx = blockIdx.x * blockDim.x + threadIdx.x;
    if (idx >= 64 * 1536) return;
    int n = idx / 1536, k = idx % 1536;
    float v = 0.f;
    if (n < 28 && k < 768) v = Wd[k * 28 + n];
    else if (n >= 28 && k >= 768) v = Wt[(k - 768) * 36 + (n - 28)];
    bf16 h = __float2bfloat16(v);
    g_Ehi[idx] = h;
    g_Elo[idx] = __float2bfloat16(v - __bfloat162float(h));
}

// --------------------- emb_pipe: K=1536 fused embeddings -------------------
// 128-row tile, 2-deep A (fp32) + B pipeline. Output -> bf16 planes, lrelu.
#define E_ST 512
#define E_B  70144
#define E_TOTAL 107008

template <int NT0, int NT1>
__device__ __forceinline__ void emb_mma(const char* stg, uint32_t ubh,
                                        uint32_t ubl, int wid, int lane,
                                        float acc[8][4]) {
    int lb = lane & 7;
    int lbm = ((lane >> 3) & 1) * 16;
#pragma unroll
    for (int ks = 0; ks < 4; ks++) {
        uint32_t ah[4], al[4];
        frag_cvt(ah, al, stg, wid * 16, ks, lane);
#pragma unroll
        for (int nt = NT0; nt < NT1; nt++) {
            uint32_t bo = (uint32_t)((nt * 8 + lb) * 144 + ks * 32 + lbm);
            uint32_t bh0, bh1, bl0, bl1;
            ldsm2(bh0, bh1, ubh + bo);
            ldsm2(bl0, bl1, ubl + bo);
            mma16816(acc[nt], ah, bh0, bh1);
            mma16816(acc[nt], ah, bl0, bl1);
            mma16816(acc[nt], al, bh0, bh1);
        }
    }
}

__global__ void __launch_bounds__(256, 2)
emb_pipe(const float* __restrict__ des, const float* __restrict__ tweet,
         const float* __restrict__ bd, const float* __restrict__ bt,
         bf16* __restrict__ Ch, bf16* __restrict__ Cl, int M) {
    extern __shared__ char sm[];
    uint32_t sb = (uint32_t)__cvta_generic_to_shared(sm);
    float* sbias = (float*)sm;
    int tid = threadIdx.x, lane = tid & 31, wid = tid >> 5;
    int m0 = blockIdx.x * 128;
    if (tid < 64) sbias[tid] = (tid < 28) ? bd[tid] : bt[tid - 28];

    auto issue = [&](int kc) {
        const float* src = (kc < 12) ? des : tweet;
        int k0 = (kc < 12) ? kc * 64 : (kc - 12) * 64;
        uint32_t sdst = sb + E_ST + (uint32_t)((kc & 1) * 34816);
#pragma unroll
        for (int i = 0; i < 8; i++) {
            int t = tid + i * 256;
            int row = t >> 4, cq = t & 15;
            int gr = m0 + row;
            uint32_t dst = sdst + (uint32_t)(row * 272 + cq * 16);
            const float* s = src + (size_t)(gr < M ? gr : 0) * 768 + k0 + cq * 4;
            int szz = (gr < M) ? 16 : 0;
            asm volatile("cp.async.cg.shared.global [%0], [%1], 16, %2;"
                         :: "r"(dst), "l"(s), "r"(szz));
        }
        int ke = kc * 64;
        uint32_t bdst = sb + E_B + (uint32_t)((kc & 1) * 18432);
#pragma unroll
        for (int i = 0; i < 4; i++) {
            int t = tid + i * 256;
            int hl = t >> 9;
            int u = t & 511;
            int n = u >> 3, kb = u & 7;
            const bf16* s = (hl ? g_Elo : g_Ehi) + n * 1536 + ke + kb * 8;
            uint32_t dst = bdst + (uint32_t)(hl * 9216 + n * 144 + kb * 16);
            asm volatile("cp.async.ca.shared.global [%0], [%1], 16;"
                         :: "r"(dst), "l"(s));
        }
    };

    issue(0); asm volatile("cp.async.commit_group;" ::: "memory");
    issue(1); asm volatile("cp.async.commit_group;" ::: "memory");

    float acc[8][4];
#pragma unroll
    for (int nt = 0; nt < 8; nt++)
#pragma unroll
        for (int q = 0; q < 4; q++) acc[nt][q] = 0.f;

    for (int kc = 0; kc < 24; kc++) {
        asm volatile("cp.async.wait_group 1;" ::: "memory");
        __syncthreads();
        const char* stg = sm + E_ST + (kc & 1) * 34816;
        uint32_t ubh = sb + E_B + (uint32_t)((kc & 1) * 18432);
        uint32_t ubl = ubh + 9216;
        if (kc < 12) emb_mma<0, 4>(stg, ubh, ubl, wid, lane, acc);
        else         emb_mma<3, 8>(stg, ubh, ubl, wid, lane, acc);
        __syncthreads();
        if (kc + 2 < 24) issue(kc + 2);
        asm volatile("cp.async.commit_group;" ::: "memory");
    }

#pragma unroll
    for (int nt = 0; nt < 8; nt++) {
        int c = nt * 8 + (lane & 3) * 2;
        float2 b2 = make_float2(sbias[c], sbias[c + 1]);
        int r0 = m0 + wid * 16 + (lane >> 2);
        if (r0 < M)
            store_split(Ch, Cl, (size_t)r0 * 128 + c,
                        lrelu(acc[nt][0] + b2.x), lrelu(acc[nt][1] + b2.y));
        if (r0 + 8 < M)
            store_split(Ch, Cl, (size_t)(r0 + 8) * 128 + c,
                        lrelu(acc[nt][2] + b2.x), lrelu(acc[nt][3] + b2.y));
    }
}

// ------------- sq_pipe: square (K=128) / layer (K=384) GEMMs ---------------
// Inputs are bf16 planes (h,l).  64-row M-tile, warp n-halves, 3 blocks/SM.
// MODE 0: out = act(x @ W[matBase] + bias)              (NC=2 chunks)
// MODE 1: out = x@W[mb] + z0@W[mb+1] + z1@W[mb+2] + b   (NC=6 chunks)
// FINAL : lrelu then project [128->2] with W2/b2 into out2=[M,2].
// smem: hdr 2048 | stage[2] 2x18432 (h 9216 + l 9216) | Bh 18432 | Bl 18432
#define SQ_ST  2048
#define SQ_BH  38912
#define SQ_BL  57344
#define SQ_TOTAL 75776

template <int MODE, bool ACT, bool FINAL>
__global__ void __launch_bounds__(256, 3)
sq_pipe(const bf16* __restrict__ xh, const bf16* __restrict__ xl,
        const bf16* __restrict__ zh, const bf16* __restrict__ zl,
        int matBase, const float* __restrict__ bias,
        bf16* __restrict__ oh, bf16* __restrict__ ol,
        float* __restrict__ out2,
        const float* __restrict__ W2, const float* __restrict__ b2, int M) {
    constexpr int NC = (MODE == 1) ? 6 : 2;
    extern __shared__ char sm[];
    uint32_t sb = (uint32_t)__cvta_generic_to_shared(sm);
    float* sbias = (float*)sm;
    float* sw2   = (float*)(sm + 512);
    float* sb2   = (float*)(sm + 1536);
    int tid = threadIdx.x, lane = tid & 31, wid = tid >> 5;
    int half = wid >> 2;
    int m0 = blockIdx.x * 64;

    if (tid < 128) sbias[tid] = bias[tid];
    if (FINAL) {
        if (tid < 256) sw2[tid] = W2[tid];
        if (tid < 2) sb2[tid] = b2[tid];
    }

    auto issueA = [&](int c) {
        if (c >= NC) return;
        const bf16 *sh, *sl; int rs, co;
        if (MODE == 0) { sh = xh; sl = xl; rs = 128; co = c * 64; }
        else {
            int p = c >> 1, h = c & 1;
            if (p == 0) { sh = xh; sl = xl; rs = 128; co = h * 64; }
            else { sh = zh; sl = zl; rs = 256; co = (p - 1) * 128 + h * 64; }
        }
        uint32_t sdst = sb + SQ_ST + (uint32_t)((c & 1) * 18432);
#pragma unroll
        for (int i = 0; i < 4; i++) {
            int t = tid + i * 256;          // 1024 granules: 2 planes x 64 x 8
            int pl = t >> 9;
            int u = t & 511;
            int row = u >> 3, g = u & 7;
            int gr = m0 + row;
            const bf16* s = (pl ? sl : sh) + (size_t)(gr < M ? gr : 0) * rs +
                            co + g * 8;
            uint32_t dst = sdst + (uint32_t)(pl * 9216 + row * 144 + g * 16);
            int szz = (gr < M) ? 16 : 0;
            asm volatile("cp.async.cg.shared.global [%0], [%1], 16, %2;"
                         :: "r"(dst), "l"(s), "r"(szz));
        }
    };

    issueA(0); asm volatile("cp.async.commit_group;" ::: "memory");
    issueA(1); asm volatile("cp.async.commit_group;" ::: "memory");

    float acc[8][4];
#pragma unroll
    for (int nt = 0; nt < 8; nt++)
#pragma unroll
        for (int q = 0; q < 4; q++) acc[nt][q] = 0.f;

    int la = ((lane >> 3) & 1) * 8 + (lane & 7);
    int lc = (lane >> 4) * 16;
    int lb = lane & 7;
    int lbm = ((lane >> 3) & 1) * 16;

    for (int c = 0; c < NC; c++) {
        asm volatile("cp.async.wait_group 1;" ::: "memory");
        __syncthreads();
        // B(c): LDG from L2-resident prepped weights -> smem
        int p = (MODE == 1) ? (c >> 1) : 0;
        int h = (MODE == 1) ? (c & 1) : c;
        const bf16* bhp = g_Whi + (size_t)(matBase + p) * 16384 + h * 64;
        const bf16* blp = g_Wlo + (size_t)(matBase + p) * 16384 + h * 64;
#pragma unroll
        for (int i = 0; i < 8; i++) {
            int t = tid + i * 256;
            int hl = t >> 10;
            int u = t & 1023;
            int n = u >> 3, kb = u & 7;
            const bf16* s = (hl ? blp : bhp) + n * 128 + kb * 8;
            *(uint4*)(sm + (hl ? SQ_BL : SQ_BH) + n * 144 + kb * 16) =
                *(const uint4*)s;
        }
        __syncthreads();
        uint32_t ust = sb + SQ_ST + (uint32_t)((c & 1) * 18432);
#pragma unroll
        for (int ks = 0; ks < 4; ks++) {
            uint32_t ao = ust + (uint32_t)(((wid & 3) * 16 + la) * 144 +
                                           ks * 32 + lc);
            uint32_t ah[4], al[4];
            ldsm4(ah, ao);
            ldsm4(al, ao + 9216);
#pragma unroll
            for (int nt = 0; nt < 8; nt++) {
                uint32_t bo = (uint32_t)((half * 64 + nt * 8 + lb) * 144 +
                                         ks * 32 + lbm);
                uint32_t bh0, bh1, bl0, bl1;
                ldsm2(bh0, bh1, sb + SQ_BH + bo);
                ldsm2(bl0, bl1, sb + SQ_BL + bo);
                mma16816(acc[nt], ah, bh0, bh1);
                mma16816(acc[nt], ah, bl0, bl1);
                mma16816(acc[nt], al, bh0, bh1);
            }
        }
        __syncthreads();
        issueA(c + 2);
        asm volatile("cp.async.commit_group;" ::: "memory");
    }

    int r0 = m0 + (wid & 3) * 16 + (lane >> 2);
    if (!FINAL) {
#pragma unroll
        for (int nt = 0; nt < 8; nt++) {
            int cc = half * 64 + nt * 8 + (lane & 3) * 2;
            float2 bb = make_float2(sbias[cc], sbias[cc + 1]);
            if (r0 < M) {
                float a = acc[nt][0] + bb.x, b = acc[nt][1] + bb.y;
                if (ACT) { a = lrelu(a); b = lrelu(b); }
                store_split(oh, ol, (size_t)r0 * 128 + cc, a, b);
            }
            if (r0 + 8 < M) {
                float a = acc[nt][2] + bb.x, b = acc[nt][3] + bb.y;
                if (ACT) { a = lrelu(a); b = lrelu(b); }
                store_split(oh, ol, (size_t)(r0 + 8) * 128 + cc, a, b);
            }
        }
    } else {
        float p0 = 0.f, p1 = 0.f, q0 = 0.f, q1 = 0.f;
#pragma unroll
        for (int nt = 0; nt < 8; nt++) {
            int cc = half * 64 + nt * 8 + (lane & 3) * 2;
            float b0 = sbias[cc], b1 = sbias[cc + 1];
            float v0 = lrelu(acc[nt][0] + b0), v1 = lrelu(acc[nt][1] + b1);
            float u0 = lrelu(acc[nt][2] + b0), u1 = lrelu(acc[nt][3] + b1);
            float w00 = sw2[cc * 2], w01 = sw2[cc * 2 + 1];
            float w10 = sw2[cc * 2 + 2], w11 = sw2[cc * 2 + 3];
            p0 += v0 * w00 + v1 * w10;  p1 += v0 * w01 + v1 * w11;
            q0 += u0 * w00 + u1 * w10;  q1 += u0 * w01 + u1 * w11;
        }
#pragma unroll
        for (int o = 1; o <= 2; o <<= 1) {
            p0 += __shfl_xor_sync(0xffffffffu, p0, o);
            p1 += __shfl_xor_sync(0xffffffffu, p1, o);
            q0 += __shfl_xor_sync(0xffffffffu, q0, o);
            q1 += __shfl_xor_sync(0xffffffffu, q1, o);
        }
        float* sred = (float*)(sm + SQ_ST);
        if ((lane & 3) == 0) {
            int rl = (wid & 3) * 16 + (lane >> 2);
            sred[half * 128 + rl * 2]           = p0;
            sred[half * 128 + rl * 2 + 1]       = p1;
            sred[half * 128 + (rl + 8) * 2]     = q0;
            sred[half * 128 + (rl + 8) * 2 + 1] = q1;
        }
        __syncthreads();
        if (tid < 128) {
            int row = tid >> 1, o = tid & 1;
            int gr = m0 + row;
            if (gr < M)
                out2[(size_t)gr * 2 + o] =
                    sred[row * 2 + o] + sred[128 + row * 2 + o] + sb2[o];
        }
    }
}

// ------------------------------- CSR build ---------------------------------
__global__ void k_zero(int n) {
    int i = blockIdx.x * blockDim.x + threadIdx.x;
    if (i < n) { g_c0[i] = 0; g_c1[i] = 0; }
}

__global__ void k_hist(const int* __restrict__ ei, const int* __restrict__ et,
                       int nE) {
    int i = blockIdx.x * blockDim.x + threadIdx.x;
    if (i >= nE) return;
    int d = ei[nE + i];
    if (et[i]) atomicAdd(&g_c1[d], 1);
    else       atomicAdd(&g_c0[d], 1);
}

__global__ void k_scan1(int n) {
    int tid = threadIdx.x;
    int i = blockIdx.x * 1024 + tid;
    int v = (i < n) ? (g_c0[i] + g_c1[i]) : 0;
    int x = v;
    int lane = tid & 31, w = tid >> 5;
#pragma unroll
    for (int d = 1; d < 32; d <<= 1) {
        int t = __shfl_up_sync(0xffffffffu, x, d);
        if (lane >= d) x += t;
    }
    __shared__ int wt[32];
    if (lane == 31) wt[w] = x;
    __syncthreads();
    if (w == 0) {
        int y = wt[lane];
#pragma unroll
        for (int d = 1; d < 32; d <<= 1) {
            int t = __shfl_up_sync(0xffffffffu, y, d);
            if (lane >= d) y += t;
        }
        wt[lane] = y;
    }
    __syncthreads();
    int off = (w > 0) ? wt[w - 1] : 0;
    int inc = x + off;
    if (i < n) g_rp[i] = inc - v;
    if (tid == 1023) g_bsum[blockIdx.x] = inc;
}

__global__ void k_scan2(int nb, int n, int nE) {
    int t = threadIdx.x;
    int lane = t & 31, w = t >> 5;
    int v = (t < nb) ? g_bsum[t] : 0;
    int x = v;
#pragma unroll
    for (int d = 1; d < 32; d <<= 1) {
        int s = __shfl_up_sync(0xffffffffu, x, d);
        if (lane >= d) x += s;
    }
    __shared__ int wt[4];
    if (lane == 31) wt[w] = x;
    __syncthreads();
    int off = 0;
    for (int k = 0; k < w; k++) off += wt[k];
    g_boff[t] = x + off - v;
    if (t == 0) g_rp[n] = nE;
}

__global__ void k_scan3(int n) {
    int i = blockIdx.x * blockDim.x + threadIdx.x;
    if (i >= n) return;
    int v = g_rp[i] + g_boff[i >> 10];
    g_rp[i] = v;
    g_cur[i] = v;
}

__global__ void k_fill(const int* __restrict__ ei, const int* __restrict__ et,
                       int nE) {
    int i = blockIdx.x * blockDim.x + threadIdx.x;
    if (i >= nE) return;
    int d = ei[nE + i];
    int pos = atomicAdd(&g_cur[d], 1);
    g_ep[pos] = (ei[i] << 1) | (et[i] ? 1 : 0);
}

// --------------------------- small embeddings ------------------------------
__global__ void k_small(const float* __restrict__ num,
                        const float* __restrict__ cat,
                        const float* __restrict__ nf,
                        const float* __restrict__ Wn, const float* __restrict__ bn,
                        const float* __restrict__ Wc, const float* __restrict__ bc,
                        const float* __restrict__ Ww, const float* __restrict__ bw,
                        bf16* __restrict__ xh, bf16* __restrict__ xl, int n) {
    int g = blockIdx.x * blockDim.x + threadIdx.x;
    if (g >= n * 64) return;
    int i = g >> 6, j = g & 63;
    float v;
    if (j < 12) {
        float s = bn[j];
#pragma unroll
        for (int k = 0; k < 7; k++)
            s = fmaf(num[(size_t)i * 7 + k], Wn[k * 12 + j], s);
        v = s;
    } else if (j < 52) {
        int c = j - 12;
        float s = bc[c];
#pragma unroll
        for (int k = 0; k < 11; k++)
            s = fmaf(cat[(size_t)i * 11 + k], Wc[k * 40 + c], s);
        v = s;
    } else {
        int c = j - 52;
        v = fmaf(nf[i], Ww[c], bw[c]);
    }
    v = lrelu(v);
    size_t idx = (size_t)i * 128 + 64 + j;
    bf16 h = __float2bfloat16(v);
    xh[idx] = h;
    xl[idx] = __float2bfloat16(v - __bfloat162float(h));
}

// --------------------- pre-aggregation: z_r = mean_r(x_src) ----------------
__global__ void k_agg2(const bf16* __restrict__ xh, const bf16* __restrict__ xl,
                       bf16* __restrict__ zh, bf16* __restrict__ zl, int n) {
    int g = blockIdx.x * blockDim.x + threadIdx.x;
    int gw = g >> 5;
    if (gw >= n) return;
    int lane = g & 31;
    int beg = g_rp[gw], end = g_rp[gw + 1];
    int c0 = g_c0[gw]; if (c0 < 1) c0 = 1;
    int c1 = g_c1[gw]; if (c1 < 1) c1 = 1;
    float w0 = 1.f / (float)c0;
    float w1 = 1.f / (float)c1;
    float4 a0 = make_float4(0.f, 0.f, 0.f, 0.f);
    float4 a1 = make_float4(0.f, 0.f, 0.f, 0.f);
    for (int e = beg; e < end; e++) {
        int p = g_ep[e];
        size_t base = (size_t)(p >> 1) * 128 + lane * 4;
        uint2 hv = *(const uint2*)(xh + base);
        uint2 lv = *(const uint2*)(xl + base);
        float x0 = __uint_as_float(hv.x << 16) + __uint_as_float(lv.x << 16);
        float x1 = __uint_as_float(hv.x & 0xffff0000u) +
                   __uint_as_float(lv.x & 0xffff0000u);
        float x2 = __uint_as_float(hv.y << 16) + __uint_as_float(lv.y << 16);
        float x3 = __uint_as_float(hv.y & 0xffff0000u) +
                   __uint_as_float(lv.y & 0xffff0000u);
        if (p & 1) { a1.x += x0; a1.y += x1; a1.z += x2; a1.w += x3; }
        else       { a0.x += x0; a0.y += x1; a0.z += x2; a0.w += x3; }
    }
    a0.x *= w0; a0.y *= w0; a0.z *= w0; a0.w *= w0;
    a1.x *= w1; a1.y *= w1; a1.z *= w1; a1.w *= w1;
    size_t zb = (size_t)gw * 256 + lane * 4;
    store_split(zh, zl, zb,       a0.x, a0.y);
    store_split(zh, zl, zb + 2,   a0.z, a0.w);
    store_split(zh, zl, zb + 128, a1.x, a1.y);
    store_split(zh, zl, zb + 130, a1.z, a1.w);
}

// --------------------------------- launch ----------------------------------
extern "C" void kernel_launch(void* const* d_in, const int* in_sizes, int n_in,
                              void* d_out, int out_size) {
    const float* des    = (const float*)d_in[0];
    const float* tweet  = (const float*)d_in[1];
    const float* num    = (const float*)d_in[2];
    const float* cat    = (const float*)d_in[3];
    const float* nf     = (const float*)d_in[4];
    const int*   ei     = (const int*)  d_in[5];
    const int*   et     = (const int*)  d_in[6];
    const float* W_des  = (const float*)d_in[7];
    const float* b_des  = (const float*)d_in[8];
    const float* W_tw   = (const float*)d_in[9];
    const float* b_tw   = (const float*)d_in[10];
    const float* W_num  = (const float*)d_in[11];
    const float* b_num  = (const float*)d_in[12];
    const float* W_cat  = (const float*)d_in[13];
    const float* b_cat  = (const float*)d_in[14];
    const float* W_new  = (const float*)d_in[15];
    const float* b_new  = (const float*)d_in[16];
    const float* W_in   = (const float*)d_in[17];
    const float* b_in   = (const float*)d_in[18];
    const float* W_root = (const float*)d_in[19];
    const float* W_rel  = (const float*)d_in[20];
    const float* b_rg   = (const float*)d_in[21];
    const float* W_o1   = (const float*)d_in[22];
    const float* b_o1   = (const float*)d_in[23];
    const float* W_o2   = (const float*)d_in[24];
    const float* b_o2   = (const float*)d_in[25];

    int nN = in_sizes[0] / 768;
    int nE = in_sizes[6];
    if (nN > NMAX) nN = NMAX;
    if (nE > EMAX) nE = EMAX;

    bf16 *xhA, *xlA, *xhB, *xlB, *zh, *zl;
    cudaGetSymbolAddress((void**)&xhA, g_xhA);
    cudaGetSymbolAddress((void**)&xlA, g_xlA);
    cudaGetSymbolAddress((void**)&xhB, g_xhB);
    cudaGetSymbolAddress((void**)&xlB, g_xlB);
    cudaGetSymbolAddress((void**)&zh, g_zh);
    cudaGetSymbolAddress((void**)&zl, g_zl);

    cudaFuncSetAttribute(emb_pipe,
                         cudaFuncAttributeMaxDynamicSharedMemorySize, E_TOTAL);
    cudaFuncSetAttribute(sq_pipe<0, true, false>,
                         cudaFuncAttributeMaxDynamicSharedMemorySize, SQ_TOTAL);
    cudaFuncSetAttribute(sq_pipe<1, false, false>,
                         cudaFuncAttributeMaxDynamicSharedMemorySize, SQ_TOTAL);
    cudaFuncSetAttribute(sq_pipe<0, true, true>,
                         cudaFuncAttributeMaxDynamicSharedMemorySize, SQ_TOTAL);

    int gm128  = (nN + 127) / 128;
    int gm64   = (nN + 63) / 64;
    int gN256  = (nN + 255) / 256;
    int gE256  = (nE + 255) / 256;
    int gScan  = (nN + 1023) / 1024;
    int gWarpN = (nN * 32 + 255) / 256;

    // weight prep
    k_wprep<<<(14 * 16384 + 255) / 256, 256>>>(W_in, W_root, W_rel, W_o1);
    k_eprep<<<(64 * 1536 + 255) / 256, 256>>>(W_des, W_tw);

    // embeddings -> planes A
    k_small<<<(nN * 64 + 255) / 256, 256>>>(num, cat, nf, W_num, b_num,
                                            W_cat, b_cat, W_new, b_new,
                                            xhA, xlA, nN);
    emb_pipe<<<gm128, 256, E_TOTAL>>>(des, tweet, b_des, b_tw, xhA, xlA, nN);

    // W_in: planes A -> planes B (lrelu)
    sq_pipe<0, true, false><<<gm64, 256, SQ_TOTAL>>>(
        xhA, xlA, nullptr, nullptr, 0, b_in, xhB, xlB,
        nullptr, nullptr, nullptr, nN);

    // CSR over dst
    k_zero<<<gN256, 256>>>(nN);
    k_hist<<<gE256, 256>>>(ei, et, nE);
    k_scan1<<<gScan, 1024>>>(nN);
    k_scan2<<<1, 128>>>(gScan, nN, nE);
    k_scan3<<<gN256, 256>>>(nN);
    k_fill<<<gE256, 256>>>(ei, et, nE);

    // 4 RGCN layers: aggregate-first, then fused K=384 GEMM
    bf16 *cxh = xhB, *cxl = xlB, *nxh = xhA, *nxl = xlA;
    for (int l = 0; l < 4; l++) {
        k_agg2<<<gWarpN, 256>>>(cxh, cxl, zh, zl, nN);
        sq_pipe<1, false, false><<<gm64, 256, SQ_TOTAL>>>(
            cxh, cxl, zh, zl, 1 + 3 * l, b_rg + (size_t)l * 128,
            nxh, nxl, nullptr, nullptr, nullptr, nN);
        bf16* t;
        t = cxh; cxh = nxh; nxh = t;
        t = cxl; cxl = nxl; nxl = t;
    }
    // after 4 swaps: current = planes B

    // W_o1 + final head fused: planes -> d_out [N,2]
    sq_pipe<0, true, true><<<gm64, 256, SQ_TOTAL>>>(
        cxh, cxl, nullptr, nullptr, 13, b_o1, nullptr, nullptr,
        (float*)d_out, W_o2, b_o2, nN);
}

// round 17
// speedup vs baseline: 1.4668x; 1.4668x over previous
#include <cuda_runtime.h>
#include <cuda_bf16.h>
#include <cstdint>

// ---------------------------------------------------------------------------
// ESABotRGCN 4-layer pipeline.  (R14 emb + R15 sq recombination)
//  - All GEMMs: mma.sync m16n8k16 bf16 (hi/lo split x3, fp32 acc), cp.async
//    fp32 stage, fragments converted from stage in registers.
//  - emb_pipe: K=1536 fused embeddings, 128-row tiles, 2-deep cp.async A+B.
//  - sq_pipe:  K=128 / K=384 GEMMs, 64-row tiles, 3 blocks/SM; W_o1 variant
//    fuses the final [128->2] head (cross-warp reduce via smem).
//  - RGCN layer: aggregate-first (mean commutes with linear map).
// ---------------------------------------------------------------------------
#define NMAX 100000
#define EMAX 600000

// ------------------------- scratch (device globals) ------------------------
__device__ float g_bufA[(size_t)NMAX * 128];
__device__ float g_bufB[(size_t)NMAX * 128];
__device__ float g_z   [(size_t)NMAX * 256];   // [z_rel0 | z_rel1]

__device__ __nv_bfloat16 g_Whi[14 * 128 * 128]; // [mat][n][k]  (W^T, split hi)
__device__ __nv_bfloat16 g_Wlo[14 * 128 * 128];
__device__ __nv_bfloat16 g_Ehi[64 * 1536];      // embedding W, block-diag
__device__ __nv_bfloat16 g_Elo[64 * 1536];

__device__ int g_c0[NMAX];
__device__ int g_c1[NMAX];
__device__ int g_rp[NMAX + 1];
__device__ int g_cur[NMAX];
__device__ int g_ep[EMAX];                     // (src<<1)|rel
__device__ int g_bsum[128];
__device__ int g_boff[128];

// ------------------------------ small helpers ------------------------------
__device__ __forceinline__ float lrelu(float v) { return fmaxf(v, 0.01f * v); }

__device__ __forceinline__ void mma16816(float* c, const uint32_t* a,
                                         uint32_t b0, uint32_t b1) {
    asm volatile(
        "mma.sync.aligned.m16n8k16.row.col.f32.bf16.bf16.f32 "
        "{%0,%1,%2,%3}, {%4,%5,%6,%7}, {%8,%9}, {%0,%1,%2,%3};"
        : "+f"(c[0]), "+f"(c[1]), "+f"(c[2]), "+f"(c[3])
        : "r"(a[0]), "r"(a[1]), "r"(a[2]), "r"(a[3]), "r"(b0), "r"(b1));
}

__device__ __forceinline__ void ldsm2(uint32_t& r0, uint32_t& r1, uint32_t a) {
    asm volatile("ldmatrix.sync.aligned.m8n8.x2.shared.b16 {%0,%1}, [%2];"
                 : "=r"(r0), "=r"(r1) : "r"(a));
}

// pack two fp32 -> bf16x2 {lo-addr=first, hi-addr=second}, rn
__device__ __forceinline__ uint32_t bfpack(float lo, float hi) {
    uint32_t r;
    asm("cvt.rn.bf16x2.f32 %0, %1, %2;" : "=r"(r) : "f"(hi), "f"(lo));
    return r;
}

// Build hi/lo bf16 A fragments (m16k16) directly from fp32 stage (272B rows).
__device__ __forceinline__ void frag_cvt(uint32_t* ah, uint32_t* al,
                                         const char* stg, int row0, int ks,
                                         int lane) {
    const char* base = stg + (row0 + (lane >> 2)) * 272 +
                       (ks * 16 + 2 * (lane & 3)) * 4;
    float2 f[4];
    f[0] = *(const float2*)base;                 // rows 0-7 , k 0-7
    f[1] = *(const float2*)(base + 8 * 272);     // rows 8-15, k 0-7
    f[2] = *(const float2*)(base + 32);          // rows 0-7 , k 8-15
    f[3] = *(const float2*)(base + 8 * 272 + 32);// rows 8-15, k 8-15
#pragma unroll
    for (int i = 0; i < 4; i++) {
        uint32_t hp = bfpack(f[i].x, f[i].y);
        float h0 = __uint_as_float(hp << 16);
        float h1 = __uint_as_float(hp & 0xffff0000u);
        ah[i] = hp;
        al[i] = bfpack(f[i].x - h0, f[i].y - h1);
    }
}

// ------------------------------- weight prep -------------------------------
__global__ void k_wprep(const float* __restrict__ Win,
                        const float* __restrict__ Wroot,
                        const float* __restrict__ Wrel,
                        const float* __restrict__ Wo1) {
    int idx = blockIdx.x * blockDim.x + threadIdx.x;
    if (idx >= 14 * 16384) return;
    int m = idx >> 14;
    int r = idx & 16383;
    int n = r >> 7, k = r & 127;
    const float* src;
    if (m == 0) src = Win;
    else if (m == 13) src = Wo1;
    else {
        int l = (m - 1) / 3, j = (m - 1) % 3;
        src = (j == 0) ? (Wroot + (size_t)l * 16384)
                       : (Wrel + (size_t)(l * 2 + (j - 1)) * 16384);
    }
    float v = src[k * 128 + n];
    __nv_bfloat16 h = __float2bfloat16(v);
    g_Whi[idx] = h;
    g_Wlo[idx] = __float2bfloat16(v - __bfloat162float(h));
}

__global__ void k_eprep(const float* __restrict__ Wd,
                        const float* __restrict__ Wt) {
    int idx = blockIdx.x * blockDim.x + threadIdx.x;
    if (idx >= 64 * 1536) return;
    int n = idx / 1536, k = idx % 1536;
    float v = 0.f;
    if (n < 28 && k < 768) v = Wd[k * 28 + n];
    else if (n >= 28 && k >= 768) v = Wt[(k - 768) * 36 + (n - 28)];
    __nv_bfloat16 h = __float2bfloat16(v);
    g_Ehi[idx] = h;
    g_Elo[idx] = __float2bfloat16(v - __bfloat162float(h));
}

// --------------------- emb_pipe: K=1536 fused embeddings -------------------
// 128-row tile, 2-deep A (fp32) + B pipeline.  (R14 configuration, 166us)
#define E_ST 512
#define E_B  70144
#define E_TOTAL 107008

template <int NT0, int NT1>
__device__ __forceinline__ void emb_mma(const char* stg, uint32_t ubh,
                                        uint32_t ubl, int wid, int lane,
                                        float acc[8][4]) {
    int lb = lane & 7;
    int lbm = ((lane >> 3) & 1) * 16;
#pragma unroll
    for (int ks = 0; ks < 4; ks++) {
        uint32_t ah[4], al[4];
        frag_cvt(ah, al, stg, wid * 16, ks, lane);
#pragma unroll
        for (int nt = NT0; nt < NT1; nt++) {
            uint32_t bo = (uint32_t)((nt * 8 + lb) * 144 + ks * 32 + lbm);
            uint32_t bh0, bh1, bl0, bl1;
            ldsm2(bh0, bh1, ubh + bo);
            ldsm2(bl0, bl1, ubl + bo);
            mma16816(acc[nt], ah, bh0, bh1);
            mma16816(acc[nt], ah, bl0, bl1);
            mma16816(acc[nt], al, bh0, bh1);
        }
    }
}

__global__ void __launch_bounds__(256, 2)
emb_pipe(const float* __restrict__ des, const float* __restrict__ tweet,
         const float* __restrict__ bd, const float* __restrict__ bt,
         float* __restrict__ C, int M) {
    extern __shared__ char sm[];
    uint32_t sb = (uint32_t)__cvta_generic_to_shared(sm);
    float* sbias = (float*)sm;
    int tid = threadIdx.x, lane = tid & 31, wid = tid >> 5;
    int m0 = blockIdx.x * 128;
    if (tid < 64) sbias[tid] = (tid < 28) ? bd[tid] : bt[tid - 28];

    auto issue = [&](int kc) {
        const float* src = (kc < 12) ? des : tweet;
        int k0 = (kc < 12) ? kc * 64 : (kc - 12) * 64;
        uint32_t sdst = sb + E_ST + (uint32_t)((kc & 1) * 34816);
#pragma unroll
        for (int i = 0; i < 8; i++) {
            int t = tid + i * 256;
            int row = t >> 4, cq = t & 15;
            int gr = m0 + row;
            uint32_t dst = sdst + (uint32_t)(row * 272 + cq * 16);
            const float* s = src + (size_t)(gr < M ? gr : 0) * 768 + k0 + cq * 4;
            int szz = (gr < M) ? 16 : 0;
            asm volatile("cp.async.cg.shared.global [%0], [%1], 16, %2;"
                         :: "r"(dst), "l"(s), "r"(szz));
        }
        int ke = kc * 64;
        uint32_t bdst = sb + E_B + (uint32_t)((kc & 1) * 18432);
#pragma unroll
        for (int i = 0; i < 4; i++) {
            int t = tid + i * 256;
            int hl = t >> 9;
            int u = t & 511;
            int n = u >> 3, kb = u & 7;
            const __nv_bfloat16* s = (hl ? g_Elo : g_Ehi) + n * 1536 + ke + kb * 8;
            uint32_t dst = bdst + (uint32_t)(hl * 9216 + n * 144 + kb * 16);
            asm volatile("cp.async.ca.shared.global [%0], [%1], 16;"
                         :: "r"(dst), "l"(s));
        }
    };

    issue(0); asm volatile("cp.async.commit_group;" ::: "memory");
    issue(1); asm volatile("cp.async.commit_group;" ::: "memory");

    float acc[8][4];
#pragma unroll
    for (int nt = 0; nt < 8; nt++)
#pragma unroll
        for (int q = 0; q < 4; q++) acc[nt][q] = 0.f;

    for (int kc = 0; kc < 24; kc++) {
        asm volatile("cp.async.wait_group 1;" ::: "memory");
        __syncthreads();
        const char* stg = sm + E_ST + (kc & 1) * 34816;
        uint32_t ubh = sb + E_B + (uint32_t)((kc & 1) * 18432);
        uint32_t ubl = ubh + 9216;
        if (kc < 12) emb_mma<0, 4>(stg, ubh, ubl, wid, lane, acc);
        else         emb_mma<3, 8>(stg, ubh, ubl, wid, lane, acc);
        __syncthreads();
        if (kc + 2 < 24) issue(kc + 2);
        asm volatile("cp.async.commit_group;" ::: "memory");
    }

#pragma unroll
    for (int nt = 0; nt < 8; nt++) {
        int c = nt * 8 + (lane & 3) * 2;
        float2 b2 = make_float2(sbias[c], sbias[c + 1]);
        int r0 = m0 + wid * 16 + (lane >> 2);
        if (r0 < M) {
            float2 o = make_float2(lrelu(acc[nt][0] + b2.x),
                                   lrelu(acc[nt][1] + b2.y));
            *(float2*)&C[(size_t)r0 * 128 + c] = o;
        }
        if (r0 + 8 < M) {
            float2 o = make_float2(lrelu(acc[nt][2] + b2.x),
                                   lrelu(acc[nt][3] + b2.y));
            *(float2*)&C[(size_t)(r0 + 8) * 128 + c] = o;
        }
    }
}

// ------------- sq_pipe: square (K=128) / layer (K=384) GEMMs ---------------
// 64-row M-tile, warp n-halves.  3 blocks/SM.  (R15 configuration)
// MODE 0: out = act(x @ W[matBase] + bias)              (NC=2 chunks)
// MODE 1: out = x@W[mb] + z0@W[mb+1] + z1@W[mb+2] + b   (NC=6 chunks)
// FINAL : lrelu then project [128->2] with W2/b2 into C=[M,2].
// smem: hdr 2048 | stage[2] 2x17408 | Bh 18432 | Bl 18432  = 73728
#define SQ_ST  2048
#define SQ_BH  36864
#define SQ_BL  55296
#define SQ_TOTAL 73728

template <int MODE, bool ACT, bool FINAL>
__global__ void __launch_bounds__(256, 3)
sq_pipe(const float* __restrict__ x, const float* __restrict__ z, int matBase,
        const float* __restrict__ bias, float* __restrict__ C,
        const float* __restrict__ W2, const float* __restrict__ b2, int M) {
    constexpr int NC = (MODE == 1) ? 6 : 2;
    extern __shared__ char sm[];
    uint32_t sb = (uint32_t)__cvta_generic_to_shared(sm);
    float* sbias = (float*)sm;                 // 128 floats
    float* sw2   = (float*)(sm + 512);         // 256 floats (FINAL)
    float* sb2   = (float*)(sm + 1536);        // 2 floats   (FINAL)
    int tid = threadIdx.x, lane = tid & 31, wid = tid >> 5;
    int half = wid >> 2;
    int m0 = blockIdx.x * 64;

    if (tid < 128) sbias[tid] = bias[tid];
    if (FINAL) {
        if (tid < 256) sw2[tid] = W2[tid];
        if (tid < 2) sb2[tid] = b2[tid];
    }

    auto issueA = [&](int c) {
        if (c >= NC) return;
        const float* src; int rs, co;
        if (MODE == 0) { src = x; rs = 128; co = c * 64; }
        else {
            int p = c >> 1, h = c & 1;
            if (p == 0) { src = x; rs = 128; co = h * 64; }
            else        { src = z; rs = 256; co = (p - 1) * 128 + h * 64; }
        }
        uint32_t sdst = sb + SQ_ST + (uint32_t)((c & 1) * 17408);
#pragma unroll
        for (int i = 0; i < 4; i++) {
            int t = tid + i * 256;
            int row = t >> 4, cq = t & 15;
            int gr = m0 + row;
            uint32_t dst = sdst + (uint32_t)(row * 272 + cq * 16);
            const float* s = src + (size_t)(gr < M ? gr : 0) * rs + co + cq * 4;
            int szz = (gr < M) ? 16 : 0;
            asm volatile("cp.async.cg.shared.global [%0], [%1], 16, %2;"
                         :: "r"(dst), "l"(s), "r"(szz));
        }
    };

    issueA(0); asm volatile("cp.async.commit_group;" ::: "memory");
    issueA(1); asm volatile("cp.async.commit_group;" ::: "memory");

    float acc[8][4];
#pragma unroll
    for (int nt = 0; nt < 8; nt++)
#pragma unroll
        for (int q = 0; q < 4; q++) acc[nt][q] = 0.f;

    int lb = lane & 7;
    int lbm = ((lane >> 3) & 1) * 16;

    for (int c = 0; c < NC; c++) {
        asm volatile("cp.async.wait_group 1;" ::: "memory");
        __syncthreads();
        // B(c): LDG from L2-resident prepped weights -> smem
        int p = (MODE == 1) ? (c >> 1) : 0;
        int h = (MODE == 1) ? (c & 1) : c;
        const __nv_bfloat16* bhp = g_Whi + (size_t)(matBase + p) * 16384 + h * 64;
        const __nv_bfloat16* blp = g_Wlo + (size_t)(matBase + p) * 16384 + h * 64;
#pragma unroll
        for (int i = 0; i < 8; i++) {
            int t = tid + i * 256;
            int hl = t >> 10;
            int u = t & 1023;
            int n = u >> 3, kb = u & 7;
            const __nv_bfloat16* s = (hl ? blp : bhp) + n * 128 + kb * 8;
            *(uint4*)(sm + (hl ? SQ_BL : SQ_BH) + n * 144 + kb * 16) =
                *(const uint4*)s;
        }
        __syncthreads();
        const char* stg = sm + SQ_ST + (c & 1) * 17408;
#pragma unroll
        for (int ks = 0; ks < 4; ks++) {
            uint32_t ah[4], al[4];
            frag_cvt(ah, al, stg, (wid & 3) * 16, ks, lane);
#pragma unroll
            for (int nt = 0; nt < 8; nt++) {
                uint32_t bo = (uint32_t)((half * 64 + nt * 8 + lb) * 144 +
                                         ks * 32 + lbm);
                uint32_t bh0, bh1, bl0, bl1;
                ldsm2(bh0, bh1, sb + SQ_BH + bo);
                ldsm2(bl0, bl1, sb + SQ_BL + bo);
                mma16816(acc[nt], ah, bh0, bh1);
                mma16816(acc[nt], ah, bl0, bl1);
                mma16816(acc[nt], al, bh0, bh1);
            }
        }
        __syncthreads();
        issueA(c + 2);
        asm volatile("cp.async.commit_group;" ::: "memory");
    }

    int r0 = m0 + (wid & 3) * 16 + (lane >> 2);
    if (!FINAL) {
#pragma unroll
        for (int nt = 0; nt < 8; nt++) {
            int cc = half * 64 + nt * 8 + (lane & 3) * 2;
            float2 bb = make_float2(sbias[cc], sbias[cc + 1]);
            if (r0 < M) {
                float2 o = make_float2(acc[nt][0] + bb.x, acc[nt][1] + bb.y);
                if (ACT) { o.x = lrelu(o.x); o.y = lrelu(o.y); }
                *(float2*)&C[(size_t)r0 * 128 + cc] = o;
            }
            if (r0 + 8 < M) {
                float2 o = make_float2(acc[nt][2] + bb.x, acc[nt][3] + bb.y);
                if (ACT) { o.x = lrelu(o.x); o.y = lrelu(o.y); }
                *(float2*)&C[(size_t)(r0 + 8) * 128 + cc] = o;
            }
        }
    } else {
        float p0 = 0.f, p1 = 0.f, q0 = 0.f, q1 = 0.f;
#pragma unroll
        for (int nt = 0; nt < 8; nt++) {
            int cc = half * 64 + nt * 8 + (lane & 3) * 2;
            float b0 = sbias[cc], b1 = sbias[cc + 1];
            float v0 = lrelu(acc[nt][0] + b0), v1 = lrelu(acc[nt][1] + b1);
            float u0 = lrelu(acc[nt][2] + b0), u1 = lrelu(acc[nt][3] + b1);
            float w00 = sw2[cc * 2], w01 = sw2[cc * 2 + 1];
            float w10 = sw2[cc * 2 + 2], w11 = sw2[cc * 2 + 3];
            p0 += v0 * w00 + v1 * w10;  p1 += v0 * w01 + v1 * w11;
            q0 += u0 * w00 + u1 * w10;  q1 += u0 * w01 + u1 * w11;
        }
#pragma unroll
        for (int o = 1; o <= 2; o <<= 1) {
            p0 += __shfl_xor_sync(0xffffffffu, p0, o);
            p1 += __shfl_xor_sync(0xffffffffu, p1, o);
            q0 += __shfl_xor_sync(0xffffffffu, q0, o);
            q1 += __shfl_xor_sync(0xffffffffu, q1, o);
        }
        // cross-warp combine (two n-halves share rows) via reused stage smem
        float* sred = (float*)(sm + SQ_ST);       // 2 halves x 64 rows x 2
        if ((lane & 3) == 0) {
            int rl = (wid & 3) * 16 + (lane >> 2);
            sred[half * 128 + rl * 2]           = p0;
            sred[half * 128 + rl * 2 + 1]       = p1;
            sred[half * 128 + (rl + 8) * 2]     = q0;
            sred[half * 128 + (rl + 8) * 2 + 1] = q1;
        }
        __syncthreads();
        if (tid < 128) {
            int row = tid >> 1, o = tid & 1;
            int gr = m0 + row;
            if (gr < M)
                C[(size_t)gr * 2 + o] =
                    sred[row * 2 + o] + sred[128 + row * 2 + o] + sb2[o];
        }
    }
}

// ------------------------------- CSR build ---------------------------------
__global__ void k_zero(int n) {
    int i = blockIdx.x * blockDim.x + threadIdx.x;
    if (i < n) { g_c0[i] = 0; g_c1[i] = 0; }
}

__global__ void k_hist(const int* __restrict__ ei, const int* __restrict__ et,
                       int nE) {
    int i = blockIdx.x * blockDim.x + threadIdx.x;
    if (i >= nE) return;
    int d = ei[nE + i];
    if (et[i]) atomicAdd(&g_c1[d], 1);
    else       atomicAdd(&g_c0[d], 1);
}

__global__ void k_scan1(int n) {
    int tid = threadIdx.x;
    int i = blockIdx.x * 1024 + tid;
    int v = (i < n) ? (g_c0[i] + g_c1[i]) : 0;
    int x = v;
    int lane = tid & 31, w = tid >> 5;
#pragma unroll
    for (int d = 1; d < 32; d <<= 1) {
        int t = __shfl_up_sync(0xffffffffu, x, d);
        if (lane >= d) x += t;
    }
    __shared__ int wt[32];
    if (lane == 31) wt[w] = x;
    __syncthreads();
    if (w == 0) {
        int y = wt[lane];
#pragma unroll
        for (int d = 1; d < 32; d <<= 1) {
            int t = __shfl_up_sync(0xffffffffu, y, d);
            if (lane >= d) y += t;
        }
        wt[lane] = y;
    }
    __syncthreads();
    int off = (w > 0) ? wt[w - 1] : 0;
    int inc = x + off;
    if (i < n) g_rp[i] = inc - v;
    if (tid == 1023) g_bsum[blockIdx.x] = inc;
}

__global__ void k_scan2(int nb, int n, int nE) {
    int t = threadIdx.x;
    int lane = t & 31, w = t >> 5;
    int v = (t < nb) ? g_bsum[t] : 0;
    int x = v;
#pragma unroll
    for (int d = 1; d < 32; d <<= 1) {
        int s = __shfl_up_sync(0xffffffffu, x, d);
        if (lane >= d) x += s;
    }
    __shared__ int wt[4];
    if (lane == 31) wt[w] = x;
    __syncthreads();
    int off = 0;
    for (int k = 0; k < w; k++) off += wt[k];
    g_boff[t] = x + off - v;
    if (t == 0) g_rp[n] = nE;
}

__global__ void k_scan3(int n) {
    int i = blockIdx.x * blockDim.x + threadIdx.x;
    if (i >= n) return;
    int v = g_rp[i] + g_boff[i >> 10];
    g_rp[i] = v;
    g_cur[i] = v;
}

__global__ void k_fill(const int* __restrict__ ei, const int* __restrict__ et,
                       int nE) {
    int i = blockIdx.x * blockDim.x + threadIdx.x;
    if (i >= nE) return;
    int d = ei[nE + i];
    int pos = atomicAdd(&g_cur[d], 1);
    g_ep[pos] = (ei[i] << 1) | (et[i] ? 1 : 0);
}

// --------------------------- small embeddings ------------------------------
__global__ void k_small(const float* __restrict__ num,
                        const float* __restrict__ cat,
                        const float* __restrict__ nf,
                        const float* __restrict__ Wn, const float* __restrict__ bn,
                        const float* __restrict__ Wc, const float* __restrict__ bc,
                        const float* __restrict__ Ww, const float* __restrict__ bw,
                        float* __restrict__ xcat, int n) {
    int g = blockIdx.x * blockDim.x + threadIdx.x;
    if (g >= n * 64) return;
    int i = g >> 6, j = g & 63;
    float v;
    if (j < 12) {
        float s = bn[j];
#pragma unroll
        for (int k = 0; k < 7; k++)
            s = fmaf(num[(size_t)i * 7 + k], Wn[k * 12 + j], s);
        v = s;
    } else if (j < 52) {
        int c = j - 12;
        float s = bc[c];
#pragma unroll
        for (int k = 0; k < 11; k++)
            s = fmaf(cat[(size_t)i * 11 + k], Wc[k * 40 + c], s);
        v = s;
    } else {
        int c = j - 52;
        v = fmaf(nf[i], Ww[c], bw[c]);
    }
    xcat[(size_t)i * 128 + 64 + j] = lrelu(v);
}

// --------------------- pre-aggregation: z_r = mean_r(x_src) ----------------
__global__ void k_agg2(const float* __restrict__ x, float* __restrict__ z,
                       int n) {
    int g = blockIdx.x * blockDim.x + threadIdx.x;
    int gw = g >> 5;
    if (gw >= n) return;
    int lane = g & 31;
    int beg = g_rp[gw], end = g_rp[gw + 1];
    int c0 = g_c0[gw]; if (c0 < 1) c0 = 1;
    int c1 = g_c1[gw]; if (c1 < 1) c1 = 1;
    float w0 = 1.f / (float)c0;
    float w1 = 1.f / (float)c1;
    float4 a0 = make_float4(0.f, 0.f, 0.f, 0.f);
    float4 a1 = make_float4(0.f, 0.f, 0.f, 0.f);
    for (int e = beg; e < end; e++) {
        int p = g_ep[e];
        float4 v = ((const float4*)(x + (size_t)(p >> 1) * 128))[lane];
        if (p & 1) { a1.x += v.x; a1.y += v.y; a1.z += v.z; a1.w += v.w; }
        else       { a0.x += v.x; a0.y += v.y; a0.z += v.z; a0.w += v.w; }
    }
    a0.x *= w0; a0.y *= w0; a0.z *= w0; a0.w *= w0;
    a1.x *= w1; a1.y *= w1; a1.z *= w1; a1.w *= w1;
    ((float4*)(z + (size_t)gw * 256))[lane] = a0;
    ((float4*)(z + (size_t)gw * 256 + 128))[lane] = a1;
}

// --------------------------------- launch ----------------------------------
extern "C" void kernel_launch(void* const* d_in, const int* in_sizes, int n_in,
                              void* d_out, int out_size) {
    const float* des    = (const float*)d_in[0];
    const float* tweet  = (const float*)d_in[1];
    const float* num    = (const float*)d_in[2];
    const float* cat    = (const float*)d_in[3];
    const float* nf     = (const float*)d_in[4];
    const int*   ei     = (const int*)  d_in[5];
    const int*   et     = (const int*)  d_in[6];
    const float* W_des  = (const float*)d_in[7];
    const float* b_des  = (const float*)d_in[8];
    const float* W_tw   = (const float*)d_in[9];
    const float* b_tw   = (const float*)d_in[10];
    const float* W_num  = (const float*)d_in[11];
    const float* b_num  = (const float*)d_in[12];
    const float* W_cat  = (const float*)d_in[13];
    const float* b_cat  = (const float*)d_in[14];
    const float* W_new  = (const float*)d_in[15];
    const float* b_new  = (const float*)d_in[16];
    const float* W_in   = (const float*)d_in[17];
    const float* b_in   = (const float*)d_in[18];
    const float* W_root = (const float*)d_in[19];
    const float* W_rel  = (const float*)d_in[20];
    const float* b_rg   = (const float*)d_in[21];
    const float* W_o1   = (const float*)d_in[22];
    const float* b_o1   = (const float*)d_in[23];
    const float* W_o2   = (const float*)d_in[24];
    const float* b_o2   = (const float*)d_in[25];

    int nN = in_sizes[0] / 768;
    int nE = in_sizes[6];
    if (nN > NMAX) nN = NMAX;
    if (nE > EMAX) nE = EMAX;

    float *bufA, *bufB, *bufZ;
    cudaGetSymbolAddress((void**)&bufA, g_bufA);
    cudaGetSymbolAddress((void**)&bufB, g_bufB);
    cudaGetSymbolAddress((void**)&bufZ, g_z);

    cudaFuncSetAttribute(emb_pipe,
                         cudaFuncAttributeMaxDynamicSharedMemorySize, E_TOTAL);
    cudaFuncSetAttribute(sq_pipe<0, true, false>,
                         cudaFuncAttributeMaxDynamicSharedMemorySize, SQ_TOTAL);
    cudaFuncSetAttribute(sq_pipe<1, false, false>,
                         cudaFuncAttributeMaxDynamicSharedMemorySize, SQ_TOTAL);
    cudaFuncSetAttribute(sq_pipe<0, true, true>,
                         cudaFuncAttributeMaxDynamicSharedMemorySize, SQ_TOTAL);

    int gm128  = (nN + 127) / 128;
    int gm64   = (nN + 63) / 64;
    int gN256  = (nN + 255) / 256;
    int gE256  = (nE + 255) / 256;
    int gScan  = (nN + 1023) / 1024;
    int gWarpN = (nN * 32 + 255) / 256;

    // weight prep
    k_wprep<<<(14 * 16384 + 255) / 256, 256>>>(W_in, W_root, W_rel, W_o1);
    k_eprep<<<(64 * 1536 + 255) / 256, 256>>>(W_des, W_tw);

    // embeddings -> bufA
    k_small<<<(nN * 64 + 255) / 256, 256>>>(num, cat, nf, W_num, b_num,
                                            W_cat, b_cat, W_new, b_new,
                                            bufA, nN);
    emb_pipe<<<gm128, 256, E_TOTAL>>>(des, tweet, b_des, b_tw, bufA, nN);

    // W_in: bufA -> bufB, lrelu
    sq_pipe<0, true, false><<<gm64, 256, SQ_TOTAL>>>(
        bufA, nullptr, 0, b_in, bufB, nullptr, nullptr, nN);

    // CSR over dst
    k_zero<<<gN256, 256>>>(nN);
    k_hist<<<gE256, 256>>>(ei, et, nE);
    k_scan1<<<gScan, 1024>>>(nN);
    k_scan2<<<1, 128>>>(gScan, nN, nE);
    k_scan3<<<gN256, 256>>>(nN);
    k_fill<<<gE256, 256>>>(ei, et, nE);

    // 4 RGCN layers: aggregate x first, then fused K=384 GEMM
    float* x  = bufB;
    float* xn = bufA;
    for (int l = 0; l < 4; l++) {
        k_agg2<<<gWarpN, 256>>>(x, bufZ, nN);
        sq_pipe<1, false, false><<<gm64, 256, SQ_TOTAL>>>(
            x, bufZ, 1 + 3 * l, b_rg + (size_t)l * 128, xn,
            nullptr, nullptr, nN);
        float* t = x; x = xn; xn = t;
    }
    // after 4 swaps: x == bufB

    // W_o1 + final head fused: x -> d_out [N,2]
    sq_pipe<0, true, true><<<gm64, 256, SQ_TOTAL>>>(
        x, nullptr, 13, b_o1, (float*)d_out, W_o2, b_o2, nN);
}